// round 16
// baseline (speedup 1.0000x reference)
#include <cuda_runtime.h>
#include <cuda_fp16.h>
#include <math.h>
#include <stdint.h>

// Problem dims
#define Bsz  256
#define Tsz  256
#define INsz 4
#define HPsz 64
#define Esz  512
#define Hsz  1024
#define Dsz  4
#define ROWS (Bsz * Tsz)   // 65536

// ---------------------------------------------------------------------------
// Scratch (device globals; no allocation allowed)
// ---------------------------------------------------------------------------
__device__ float  g_x  [(size_t)ROWS * Esz];
__device__ __half g_xhi[(size_t)ROWS * Esz];
__device__ __half g_xlo[(size_t)ROWS * Esz];
__device__ float  g_h1 [(size_t)ROWS * Hsz];
__device__ __half g_spk[(size_t)ROWS * Hsz];
__device__ float  g_h2 [(size_t)ROWS * Esz];
__device__ float  g_psum[(size_t)ROWS * 8];   // stride 8 for BOTH gemms
__device__ float  g_psq [(size_t)ROWS * 8];
__device__ __half g_w1hi[(size_t)Dsz * Hsz * Esz];
__device__ __half g_w1lo[(size_t)Dsz * Hsz * Esz];
__device__ __half g_w2hi[(size_t)Dsz * Esz * Hsz];
__device__ __half g_w2lo[(size_t)Dsz * Esz * Hsz];

// ---------------------------------------------------------------------------
// Helpers
// ---------------------------------------------------------------------------
__device__ __forceinline__ uint32_t sw128(uint32_t b) { return b ^ ((b >> 3) & 0x70); }

__device__ __forceinline__ uint32_t s2u(const void* p) {
    uint32_t a;
    asm("{ .reg .u64 t; cvta.to.shared.u64 t, %1; cvt.u32.u64 %0, t; }" : "=r"(a) : "l"(p));
    return a;
}

__device__ __forceinline__ void cp16(uint32_t saddr, const void* g) {
    asm volatile("cp.async.cg.shared.global [%0], [%1], 16;" :: "r"(saddr), "l"(g));
}

#define LDSM4(r0, r1, r2, r3, addr)                                           \
    asm volatile("ldmatrix.sync.aligned.m8n8.x4.shared.b16 {%0,%1,%2,%3}, [%4];" \
                 : "=r"(r0), "=r"(r1), "=r"(r2), "=r"(r3) : "r"(addr))

#define MMA16816(d, a, b)                                                     \
    asm volatile(                                                             \
        "mma.sync.aligned.m16n8k16.row.col.f32.f16.f16.f32 "                  \
        "{%0,%1,%2,%3},{%4,%5,%6,%7},{%8,%9},{%0,%1,%2,%3};"                  \
        : "+f"((d)[0]), "+f"((d)[1]), "+f"((d)[2]), "+f"((d)[3])              \
        : "r"((a)[0]), "r"((a)[1]), "r"((a)[2]), "r"((a)[3]),                 \
          "r"((b)[0]), "r"((b)[1]))

// ---------------------------------------------------------------------------
// Split+transpose weights
// ---------------------------------------------------------------------------
__global__ void split_w(const float* __restrict__ W, __half* __restrict__ hi,
                        __half* __restrict__ lo, int K, int N) {
    int idx = blockIdx.x * blockDim.x + threadIdx.x;
    if (idx >= K * N) return;
    size_t lofs = (size_t)blockIdx.y * K * N;
    int k = idx / N, n = idx % N;
    float w = W[lofs + idx];
    __half h = __float2half_rn(w);
    hi[lofs + (size_t)n * K + k] = h;
    lo[lofs + (size_t)n * K + k] = __float2half_rn(w - __half2float(h));
}

// ---------------------------------------------------------------------------
// GEMM: C = Ahi@Bhi^T + Ahi@Blo^T (+ Alo@Bhi^T) + bias; epilogue emits
// per-tile LN partials (stride-8). CTA 256x128, warp 64x64, BK=64, 2-stage.
// ---------------------------------------------------------------------------
template <int TERMS> struct G2 {
    static constexpr int AHI = 0;
    static constexpr int ALO = 32768;
    static constexpr int BHI = (TERMS == 3) ? 65536 : 32768;
    static constexpr int BLO = BHI + 16384;
    static constexpr int STG = BLO + 16384;      // 96 KB / 64 KB
    static constexpr int STATS = 2 * STG;
    static constexpr int TOT = STATS + 16384;    // 208 KB / 144 KB
};

template <int TERMS, int KK>
__device__ __forceinline__ void load_stage256(uint32_t sbase,
                                              const __half* A, const __half* Al,
                                              const __half* B, const __half* Bl,
                                              int k0, int tid) {
#pragma unroll
    for (int it = 0; it < 8; it++) {
        int idx = tid + it * 256;
        int r = idx >> 3, c = idx & 7;
        uint32_t so = sw128((uint32_t)(r * 128 + c * 16));
        size_t go = (size_t)r * KK + k0 + c * 8;
        cp16(sbase + G2<TERMS>::AHI + so, A + go);
        if (TERMS == 3) cp16(sbase + G2<TERMS>::ALO + so, Al + go);
    }
#pragma unroll
    for (int it = 0; it < 4; it++) {
        int idx = tid + it * 256;
        int r = idx >> 3, c = idx & 7;
        uint32_t so = sw128((uint32_t)(r * 128 + c * 16));
        size_t go = (size_t)r * KK + k0 + c * 8;
        cp16(sbase + G2<TERMS>::BHI + so, B + go);
        cp16(sbase + G2<TERMS>::BLO + so, Bl + go);
    }
    asm volatile("cp.async.commit_group;" ::: "memory");
}

template <int TERMS, int TILES, int KK, int NTOT>
__global__ void __launch_bounds__(256, 1)
gemm_hs256(const __half* __restrict__ Ahi, const __half* __restrict__ Alo,
           const __half* __restrict__ Bhi, const __half* __restrict__ Blo,
           const float* __restrict__ bias, float* __restrict__ C,
           float* __restrict__ psum, float* __restrict__ psq) {
    using GG = G2<TERMS>;
    extern __shared__ char smc[];
    uint32_t sb = s2u(smc);
    float* ssum = (float*)(smc + GG::STATS);
    float* ssq  = (float*)(smc + GG::STATS + 8192);
    int tid = threadIdx.x;
    int wid = tid >> 5, lane = tid & 31;
    int warp_m = wid >> 1, warp_n = wid & 1;
    int bxg = blockIdx.x, by = blockIdx.y;
    int row_in = lane & 7, grp = lane >> 3;

    constexpr int NC = KK / 64;
    constexpr int TC = TILES * NC;

    const __half* Ah = Ahi + (size_t)(by * 256) * KK;
    const __half* Al = Alo + (size_t)(by * 256) * KK;

    float acc[4][8][4] = {};
    uint32_t ahi[4][4], alo[4][4], bhi[8][2], blo[8][2];

    {
        const __half* Bh0 = Bhi + (size_t)(bxg * TILES * 128) * KK;
        const __half* Bl0 = Blo + (size_t)(bxg * TILES * 128) * KK;
        load_stage256<TERMS, KK>(sb, Ah, Al, Bh0, Bl0, 0, tid);
    }

    for (int g = 0; g < TC; g++) {
        int tile = g / NC, c = g % NC;
        asm volatile("cp.async.wait_group 0;" ::: "memory");
        __syncthreads();

        int g1 = g + 1;
        if (g1 < TC) {
            int t1 = g1 / NC, c1 = g1 % NC;
            const __half* Bh1 = Bhi + (size_t)((bxg * TILES + t1) * 128) * KK;
            const __half* Bl1 = Blo + (size_t)((bxg * TILES + t1) * 128) * KK;
            load_stage256<TERMS, KK>(sb + (g1 & 1) * GG::STG, Ah, Al, Bh1, Bl1, c1 * 64, tid);
        }

        uint32_t stg = sb + (g & 1) * GG::STG;
#pragma unroll
        for (int ks = 0; ks < 4; ks++) {
#pragma unroll
            for (int mf = 0; mf < 4; mf++) {
                int r = warp_m * 64 + mf * 16 + (grp & 1) * 8 + row_in;
                int kb = ks * 32 + (grp >> 1) * 16;
                uint32_t off = sw128((uint32_t)(r * 128 + kb));
                LDSM4(ahi[mf][0], ahi[mf][1], ahi[mf][2], ahi[mf][3], stg + GG::AHI + off);
                if (TERMS == 3)
                    LDSM4(alo[mf][0], alo[mf][1], alo[mf][2], alo[mf][3],
                          stg + GG::ALO + off);
            }
#pragma unroll
            for (int p = 0; p < 4; p++) {
                int r = warp_n * 64 + p * 16 + (grp >> 1) * 8 + row_in;
                int kb = ks * 32 + (grp & 1) * 16;
                uint32_t off = sw128((uint32_t)(r * 128 + kb));
                uint32_t t0, t1, t2, t3;
                LDSM4(t0, t1, t2, t3, stg + GG::BHI + off);
                bhi[2 * p][0] = t0; bhi[2 * p][1] = t1;
                bhi[2 * p + 1][0] = t2; bhi[2 * p + 1][1] = t3;
                LDSM4(t0, t1, t2, t3, stg + GG::BLO + off);
                blo[2 * p][0] = t0; blo[2 * p][1] = t1;
                blo[2 * p + 1][0] = t2; blo[2 * p + 1][1] = t3;
            }
            // per-acc order: hibhi -> hiblo -> lobhi (unchanged)
#pragma unroll
            for (int mf = 0; mf < 4; mf++)
#pragma unroll
                for (int nf = 0; nf < 8; nf++)
                    MMA16816(acc[mf][nf], ahi[mf], bhi[nf]);
#pragma unroll
            for (int mf = 0; mf < 4; mf++)
#pragma unroll
                for (int nf = 0; nf < 8; nf++)
                    MMA16816(acc[mf][nf], ahi[mf], blo[nf]);
            if (TERMS == 3) {
#pragma unroll
                for (int mf = 0; mf < 4; mf++)
#pragma unroll
                    for (int nf = 0; nf < 8; nf++)
                        MMA16816(acc[mf][nf], alo[mf], bhi[nf]);
            }
        }

        if (c == NC - 1) {
            int col_base = (bxg * TILES + tile) * 128 + warp_n * 64 + (lane & 3) * 2;
            int row_base = by * 256 + warp_m * 64 + (lane >> 2);
            int contrib = warp_n * 4 + (lane & 3);
#pragma unroll
            for (int mf = 0; mf < 4; mf++) {
                float lsA = 0.f, lqA = 0.f, lsB = 0.f, lqB = 0.f;
#pragma unroll
                for (int nf = 0; nf < 8; nf++) {
                    int col = col_base + nf * 8;
                    float b0 = __ldg(bias + col), b1 = __ldg(bias + col + 1);
                    int r0 = row_base + mf * 16;
                    float2 v0 = { acc[mf][nf][0] + b0, acc[mf][nf][1] + b1 };
                    float2 v1 = { acc[mf][nf][2] + b0, acc[mf][nf][3] + b1 };
                    *(float2*)(C + (size_t)r0 * NTOT + col) = v0;
                    *(float2*)(C + (size_t)(r0 + 8) * NTOT + col) = v1;
                    lsA += v0.x + v0.y; lqA += v0.x * v0.x + v0.y * v0.y;
                    lsB += v1.x + v1.y; lqB += v1.x * v1.x + v1.y * v1.y;
                }
                int rA = warp_m * 64 + mf * 16 + (lane >> 2);
                ssum[rA * 8 + contrib] = lsA;
                ssq [rA * 8 + contrib] = lqA;
                ssum[(rA + 8) * 8 + contrib] = lsB;
                ssq [(rA + 8) * 8 + contrib] = lqB;
#pragma unroll
                for (int nf = 0; nf < 8; nf++)
#pragma unroll
                    for (int q = 0; q < 4; q++) acc[mf][nf][q] = 0.0f;
            }
            __syncthreads();
            {
                float s = 0.f, q = 0.f;
#pragma unroll
                for (int p = 0; p < 8; p++) { s += ssum[tid * 8 + p]; q += ssq[tid * 8 + p]; }
                int tcol = bxg * TILES + tile;
                size_t row = (size_t)(by * 256 + tid);
                psum[row * 8 + tcol] = s;   // uniform stride 8
                psq [row * 8 + tcol] = q;
            }
            __syncthreads();
        }
    }
}

// ---------------------------------------------------------------------------
// Fused stats + LIF: one block per (batch, channel-quarter) -> 1024 blocks.
// Scalar channel per thread; explicit t+1 prefetch. Arithmetic identical.
// ---------------------------------------------------------------------------
__global__ void __launch_bounds__(256)
lif_fused(const float* __restrict__ h,
          const float* __restrict__ psum, const float* __restrict__ psq,
          const float* __restrict__ gam, const float* __restrict__ bet,
          __half* __restrict__ spk) {
    __shared__ float smean[256], srstd[256];
    int tid = threadIdx.x;
    int b = blockIdx.x >> 2, qh = blockIdx.x & 3;
    {
        size_t row = (size_t)b * 256 + tid;
        float s = 0.f, q = 0.f;
#pragma unroll
        for (int p = 0; p < 8; p++) { s += psum[row * 8 + p]; q += psq[row * 8 + p]; }
        float m = s * (1.0f / Hsz);
        float var = fmaxf(q * (1.0f / Hsz) - m * m, 0.0f);
        smean[tid] = m;
        srstd[tid] = 1.0f / sqrtf(var + 1e-5f);
    }
    __syncthreads();

    int j = qh * 256 + tid;
    float gg = gam[j], bb = bet[j];
    float v = 0.f;
    size_t base = (size_t)b * Tsz * Hsz + j;
    float cur = h[base];
#pragma unroll 4
    for (int t = 0; t < Tsz; t++) {
        float nxt = (t + 1 < Tsz) ? h[base + (size_t)(t + 1) * Hsz] : 0.f;
        float m = smean[t], inv = srstd[t];
        float n = (cur - m) * inv * gg + bb;
        v = v + (n - v) * 0.5f;
        float sp = 0.f;
        if (v >= 1.0f) { sp = 1.0f; v = 0.f; }
        spk[base + (size_t)t * Hsz] = __float2half_rn(sp);
        cur = nxt;
    }
}

// Fused stats + LIF + residual add + sparse split refresh; optional fused
// "last timestep -> out" emission (value-identical to last_kernel).
template <bool LAST>
__global__ void __launch_bounds__(256)
lifadd_fused(const float* __restrict__ h,
             const float* __restrict__ psum, const float* __restrict__ psq,
             const float* __restrict__ gam, const float* __restrict__ bet,
             float* __restrict__ x, __half* __restrict__ xhi,
             __half* __restrict__ xlo, float* __restrict__ out) {
    __shared__ float smean[256], srstd[256];
    int tid = threadIdx.x;
    int b = blockIdx.x >> 1, hh = blockIdx.x & 1;
    {
        size_t row = (size_t)b * 256 + tid;
        float s = 0.f, q = 0.f;
#pragma unroll
        for (int p = 0; p < 4; p++) { s += psum[row * 8 + p]; q += psq[row * 8 + p]; }
        float m = s * (1.0f / Esz);
        float var = fmaxf(q * (1.0f / Esz) - m * m, 0.0f);
        smean[tid] = m;
        srstd[tid] = 1.0f / sqrtf(var + 1e-5f);
    }
    __syncthreads();

    int j = hh * 256 + tid;
    float gg = gam[j], bb = bet[j];
    float v = 0.f;
    size_t base = (size_t)b * Tsz * Esz + j;
    float cur = h[base];
#pragma unroll 4
    for (int t = 0; t < Tsz; t++) {
        float nxt = (t + 1 < Tsz) ? h[base + (size_t)(t + 1) * Esz] : 0.f;
        float m = smean[t], inv = srstd[t];
        float n = (cur - m) * inv * gg + bb;
        v = v + (n - v) * 0.5f;
        size_t o = base + (size_t)t * Esz;
        if (LAST && t == Tsz - 1) {
            // value-identical to: (maybe update x) then out = x[o]
            float xv = x[o];
            if (v >= 1.0f) {
                v = 0.f;
                xv += 1.0f;
                x[o] = xv;
                __half hv = __float2half_rn(xv);
                xhi[o] = hv;
                xlo[o] = __float2half_rn(xv - __half2float(hv));
            }
            out[(size_t)b * Esz + j] = xv;
        } else if (v >= 1.0f) {
            v = 0.f;
            float xv = x[o] + 1.0f;
            x[o] = xv;
            __half hv = __float2half_rn(xv);
            xhi[o] = hv;
            xlo[o] = __float2half_rn(xv - __half2float(hv));
        }
        cur = nxt;
    }
}

// ---------------------------------------------------------------------------
// Input projector, tiled (16 rows/block, W2 read once per block)
// ---------------------------------------------------------------------------
#define PR 16
__global__ void __launch_bounds__(256)
proj_kernel(const float* __restrict__ hist,
            const float* __restrict__ W1, const float* __restrict__ b1,
            const float* __restrict__ W2, const float* __restrict__ b2,
            float* __restrict__ out,
            __half* __restrict__ ohi, __half* __restrict__ olo) {
    __shared__ float hs[PR * INsz];
    __shared__ float hpT[HPsz][PR];
    int rb = blockIdx.x * PR;
    int tid = threadIdx.x;

    if (tid < PR * INsz) hs[tid] = hist[(size_t)rb * INsz + tid];
    __syncthreads();

#pragma unroll
    for (int i = 0; i < (PR * HPsz) / 256; i++) {
        int idx = tid + i * 256;
        int r = idx >> 6, cc = idx & 63;
        float a = b1[cc];
#pragma unroll
        for (int k = 0; k < INsz; k++) a += hs[r * INsz + k] * W1[k * HPsz + cc];
        hpT[cc][r] = 0.5f * a * (1.0f + erff(a * 0.70710678118654752440f));
    }
    __syncthreads();

    int c0 = tid * 2;
    float acc[PR][2];
    float bb0 = b2[c0], bb1 = b2[c0 + 1];
#pragma unroll
    for (int r = 0; r < PR; r++) { acc[r][0] = bb0; acc[r][1] = bb1; }

    for (int k = 0; k < HPsz; k++) {
        float2 w = *(const float2*)(W2 + (size_t)k * Esz + c0);
        float4 h0 = *(const float4*)&hpT[k][0];
        float4 h1 = *(const float4*)&hpT[k][4];
        float4 h2 = *(const float4*)&hpT[k][8];
        float4 h3 = *(const float4*)&hpT[k][12];
        float hk[PR] = { h0.x, h0.y, h0.z, h0.w, h1.x, h1.y, h1.z, h1.w,
                         h2.x, h2.y, h2.z, h2.w, h3.x, h3.y, h3.z, h3.w };
#pragma unroll
        for (int r = 0; r < PR; r++) {
            acc[r][0] += hk[r] * w.x;
            acc[r][1] += hk[r] * w.y;
        }
    }

#pragma unroll
    for (int r = 0; r < PR; r++) {
        size_t off = (size_t)(rb + r) * Esz + c0;
        float a0 = acc[r][0], a1 = acc[r][1];
        *(float2*)(out + off) = make_float2(a0, a1);
        __half h0 = __float2half_rn(a0), h1 = __float2half_rn(a1);
        *(__half2*)(ohi + off) = __halves2half2(h0, h1);
        *(__half2*)(olo + off) = __halves2half2(
            __float2half_rn(a0 - __half2float(h0)),
            __float2half_rn(a1 - __half2float(h1)));
    }
}

// ---------------------------------------------------------------------------
extern "C" void kernel_launch(void* const* d_in, const int* in_sizes, int n_in,
                              void* d_out, int out_size) {
    const float* hist  = (const float*)d_in[0];
    const float* pW1   = (const float*)d_in[1];
    const float* pb1   = (const float*)d_in[2];
    const float* pW2   = (const float*)d_in[3];
    const float* pb2   = (const float*)d_in[4];
    const float* fc1_w = (const float*)d_in[5];
    const float* fc1_b = (const float*)d_in[6];
    const float* ln1_g = (const float*)d_in[7];
    const float* ln1_b = (const float*)d_in[8];
    const float* fc2_w = (const float*)d_in[9];
    const float* fc2_b = (const float*)d_in[10];
    const float* ln2_g = (const float*)d_in[11];
    const float* ln2_b = (const float*)d_in[12];

    float *x, *h1, *h2, *psum, *psq;
    __half *xhi, *xlo, *spk, *w1hi, *w1lo, *w2hi, *w2lo;
    cudaGetSymbolAddress((void**)&x,    g_x);
    cudaGetSymbolAddress((void**)&h1,   g_h1);
    cudaGetSymbolAddress((void**)&h2,   g_h2);
    cudaGetSymbolAddress((void**)&psum, g_psum);
    cudaGetSymbolAddress((void**)&psq,  g_psq);
    cudaGetSymbolAddress((void**)&xhi,  g_xhi);
    cudaGetSymbolAddress((void**)&xlo,  g_xlo);
    cudaGetSymbolAddress((void**)&spk,  g_spk);
    cudaGetSymbolAddress((void**)&w1hi, g_w1hi);
    cudaGetSymbolAddress((void**)&w1lo, g_w1lo);
    cudaGetSymbolAddress((void**)&w2hi, g_w2hi);
    cudaGetSymbolAddress((void**)&w2lo, g_w2lo);

    auto* gk1 = gemm_hs256<3, 2, Esz, Hsz>;   // GEMM1: 2 N-tiles/CTA
    auto* gk2 = gemm_hs256<2, 1, Hsz, Esz>;   // GEMM2: 1 N-tile/CTA
    cudaFuncSetAttribute(gk1, cudaFuncAttributeMaxDynamicSharedMemorySize, G2<3>::TOT);
    cudaFuncSetAttribute(gk2, cudaFuncAttributeMaxDynamicSharedMemorySize, G2<2>::TOT);

    split_w<<<dim3((Esz * Hsz + 255) / 256, Dsz), 256>>>(fc1_w, w1hi, w1lo, Esz, Hsz);
    split_w<<<dim3((Hsz * Esz + 255) / 256, Dsz), 256>>>(fc2_w, w2hi, w2lo, Hsz, Esz);

    proj_kernel<<<ROWS / PR, 256>>>(hist, pW1, pb1, pW2, pb2, x, xhi, xlo);

    for (int d = 0; d < Dsz; d++) {
        size_t o1 = (size_t)d * Hsz * Esz;
        size_t o2 = (size_t)d * Esz * Hsz;

        gk1<<<dim3(Hsz / 128 / 2, ROWS / 256), 256, G2<3>::TOT>>>(
            xhi, xlo, w1hi + o1, w1lo + o1, fc1_b + d * Hsz, h1, psum, psq);
        lif_fused<<<Bsz * 4, 256>>>(
            h1, psum, psq, ln1_g + d * Hsz, ln1_b + d * Hsz, spk);

        gk2<<<dim3(Esz / 128, ROWS / 256), 256, G2<2>::TOT>>>(
            spk, spk, w2hi + o2, w2lo + o2, fc2_b + d * Esz, h2, psum, psq);
        if (d < Dsz - 1) {
            lifadd_fused<false><<<Bsz * 2, 256>>>(
                h2, psum, psq, ln2_g + d * Esz, ln2_b + d * Esz, x, xhi, xlo, nullptr);
        } else {
            lifadd_fused<true><<<Bsz * 2, 256>>>(
                h2, psum, psq, ln2_g + d * Esz, ln2_b + d * Esz, x, xhi, xlo,
                (float*)d_out);
        }
    }
}

// round 17
// speedup vs baseline: 1.0022x; 1.0022x over previous
#include <cuda_runtime.h>
#include <cuda_fp16.h>
#include <math.h>
#include <stdint.h>

// Problem dims
#define Bsz  256
#define Tsz  256
#define INsz 4
#define HPsz 64
#define Esz  512
#define Hsz  1024
#define Dsz  4
#define ROWS (Bsz * Tsz)   // 65536

// ---------------------------------------------------------------------------
// Scratch (device globals; no allocation allowed)
// ---------------------------------------------------------------------------
__device__ float  g_x  [(size_t)ROWS * Esz];
__device__ __half g_xhi[(size_t)ROWS * Esz];
__device__ __half g_xlo[(size_t)ROWS * Esz];
__device__ float  g_h1 [(size_t)ROWS * Hsz];
__device__ __half g_spk[(size_t)ROWS * Hsz];
__device__ float  g_h2 [(size_t)ROWS * Esz];
__device__ float  g_psum[(size_t)ROWS * 8];   // stride 8 for BOTH gemms
__device__ float  g_psq [(size_t)ROWS * 8];
__device__ __half g_w1hi[(size_t)Dsz * Hsz * Esz];
__device__ __half g_w1lo[(size_t)Dsz * Hsz * Esz];
__device__ __half g_w2hi[(size_t)Dsz * Esz * Hsz];
__device__ __half g_w2lo[(size_t)Dsz * Esz * Hsz];

// ---------------------------------------------------------------------------
// Helpers
// ---------------------------------------------------------------------------
__device__ __forceinline__ uint32_t sw128(uint32_t b) { return b ^ ((b >> 3) & 0x70); }

__device__ __forceinline__ uint32_t s2u(const void* p) {
    uint32_t a;
    asm("{ .reg .u64 t; cvta.to.shared.u64 t, %1; cvt.u32.u64 %0, t; }" : "=r"(a) : "l"(p));
    return a;
}

__device__ __forceinline__ void cp16(uint32_t saddr, const void* g) {
    asm volatile("cp.async.cg.shared.global [%0], [%1], 16;" :: "r"(saddr), "l"(g));
}

#define LDSM4(r0, r1, r2, r3, addr)                                           \
    asm volatile("ldmatrix.sync.aligned.m8n8.x4.shared.b16 {%0,%1,%2,%3}, [%4];" \
                 : "=r"(r0), "=r"(r1), "=r"(r2), "=r"(r3) : "r"(addr))

#define MMA16816(d, a, b)                                                     \
    asm volatile(                                                             \
        "mma.sync.aligned.m16n8k16.row.col.f32.f16.f16.f32 "                  \
        "{%0,%1,%2,%3},{%4,%5,%6,%7},{%8,%9},{%0,%1,%2,%3};"                  \
        : "+f"((d)[0]), "+f"((d)[1]), "+f"((d)[2]), "+f"((d)[3])              \
        : "r"((a)[0]), "r"((a)[1]), "r"((a)[2]), "r"((a)[3]),                 \
          "r"((b)[0]), "r"((b)[1]))

// ---------------------------------------------------------------------------
// Split+transpose weights
// ---------------------------------------------------------------------------
__global__ void split_w(const float* __restrict__ W, __half* __restrict__ hi,
                        __half* __restrict__ lo, int K, int N) {
    int idx = blockIdx.x * blockDim.x + threadIdx.x;
    if (idx >= K * N) return;
    size_t lofs = (size_t)blockIdx.y * K * N;
    int k = idx / N, n = idx % N;
    float w = W[lofs + idx];
    __half h = __float2half_rn(w);
    hi[lofs + (size_t)n * K + k] = h;
    lo[lofs + (size_t)n * K + k] = __float2half_rn(w - __half2float(h));
}

// ---------------------------------------------------------------------------
// GEMM: C = Ahi@Bhi^T + Ahi@Blo^T (+ Alo@Bhi^T) + bias; epilogue emits
// per-tile LN partials (stride-8). CTA 256x128, warp 64x64, BK=64, 2-stage.
// ---------------------------------------------------------------------------
template <int TERMS> struct G2 {
    static constexpr int AHI = 0;
    static constexpr int ALO = 32768;
    static constexpr int BHI = (TERMS == 3) ? 65536 : 32768;
    static constexpr int BLO = BHI + 16384;
    static constexpr int STG = BLO + 16384;      // 96 KB / 64 KB
    static constexpr int STATS = 2 * STG;
    static constexpr int TOT = STATS + 16384;    // 208 KB / 144 KB
};

template <int TERMS, int KK>
__device__ __forceinline__ void load_stage256(uint32_t sbase,
                                              const __half* A, const __half* Al,
                                              const __half* B, const __half* Bl,
                                              int k0, int tid) {
#pragma unroll
    for (int it = 0; it < 8; it++) {
        int idx = tid + it * 256;
        int r = idx >> 3, c = idx & 7;
        uint32_t so = sw128((uint32_t)(r * 128 + c * 16));
        size_t go = (size_t)r * KK + k0 + c * 8;
        cp16(sbase + G2<TERMS>::AHI + so, A + go);
        if (TERMS == 3) cp16(sbase + G2<TERMS>::ALO + so, Al + go);
    }
#pragma unroll
    for (int it = 0; it < 4; it++) {
        int idx = tid + it * 256;
        int r = idx >> 3, c = idx & 7;
        uint32_t so = sw128((uint32_t)(r * 128 + c * 16));
        size_t go = (size_t)r * KK + k0 + c * 8;
        cp16(sbase + G2<TERMS>::BHI + so, B + go);
        cp16(sbase + G2<TERMS>::BLO + so, Bl + go);
    }
    asm volatile("cp.async.commit_group;" ::: "memory");
}

template <int TERMS, int TILES, int KK, int NTOT>
__global__ void __launch_bounds__(256, 1)
gemm_hs256(const __half* __restrict__ Ahi, const __half* __restrict__ Alo,
           const __half* __restrict__ Bhi, const __half* __restrict__ Blo,
           const float* __restrict__ bias, float* __restrict__ C,
           float* __restrict__ psum, float* __restrict__ psq) {
    using GG = G2<TERMS>;
    extern __shared__ char smc[];
    uint32_t sb = s2u(smc);
    float* ssum = (float*)(smc + GG::STATS);
    float* ssq  = (float*)(smc + GG::STATS + 8192);
    int tid = threadIdx.x;
    int wid = tid >> 5, lane = tid & 31;
    int warp_m = wid >> 1, warp_n = wid & 1;
    int bxg = blockIdx.x, by = blockIdx.y;
    int row_in = lane & 7, grp = lane >> 3;

    constexpr int NC = KK / 64;
    constexpr int TC = TILES * NC;

    const __half* Ah = Ahi + (size_t)(by * 256) * KK;
    const __half* Al = Alo + (size_t)(by * 256) * KK;

    float acc[4][8][4] = {};
    uint32_t ahi[4][4], alo[4][4], bhi[8][2], blo[8][2];

    {
        const __half* Bh0 = Bhi + (size_t)(bxg * TILES * 128) * KK;
        const __half* Bl0 = Blo + (size_t)(bxg * TILES * 128) * KK;
        load_stage256<TERMS, KK>(sb, Ah, Al, Bh0, Bl0, 0, tid);
    }

    for (int g = 0; g < TC; g++) {
        int tile = g / NC, c = g % NC;
        asm volatile("cp.async.wait_group 0;" ::: "memory");
        __syncthreads();

        int g1 = g + 1;
        if (g1 < TC) {
            int t1 = g1 / NC, c1 = g1 % NC;
            const __half* Bh1 = Bhi + (size_t)((bxg * TILES + t1) * 128) * KK;
            const __half* Bl1 = Blo + (size_t)((bxg * TILES + t1) * 128) * KK;
            load_stage256<TERMS, KK>(sb + (g1 & 1) * GG::STG, Ah, Al, Bh1, Bl1, c1 * 64, tid);
        }

        uint32_t stg = sb + (g & 1) * GG::STG;
#pragma unroll
        for (int ks = 0; ks < 4; ks++) {
#pragma unroll
            for (int mf = 0; mf < 4; mf++) {
                int r = warp_m * 64 + mf * 16 + (grp & 1) * 8 + row_in;
                int kb = ks * 32 + (grp >> 1) * 16;
                uint32_t off = sw128((uint32_t)(r * 128 + kb));
                LDSM4(ahi[mf][0], ahi[mf][1], ahi[mf][2], ahi[mf][3], stg + GG::AHI + off);
                if (TERMS == 3)
                    LDSM4(alo[mf][0], alo[mf][1], alo[mf][2], alo[mf][3],
                          stg + GG::ALO + off);
            }
#pragma unroll
            for (int p = 0; p < 4; p++) {
                int r = warp_n * 64 + p * 16 + (grp >> 1) * 8 + row_in;
                int kb = ks * 32 + (grp & 1) * 16;
                uint32_t off = sw128((uint32_t)(r * 128 + kb));
                uint32_t t0, t1, t2, t3;
                LDSM4(t0, t1, t2, t3, stg + GG::BHI + off);
                bhi[2 * p][0] = t0; bhi[2 * p][1] = t1;
                bhi[2 * p + 1][0] = t2; bhi[2 * p + 1][1] = t3;
                LDSM4(t0, t1, t2, t3, stg + GG::BLO + off);
                blo[2 * p][0] = t0; blo[2 * p][1] = t1;
                blo[2 * p + 1][0] = t2; blo[2 * p + 1][1] = t3;
            }
            // per-acc order: hibhi -> hiblo -> lobhi (unchanged)
#pragma unroll
            for (int mf = 0; mf < 4; mf++)
#pragma unroll
                for (int nf = 0; nf < 8; nf++)
                    MMA16816(acc[mf][nf], ahi[mf], bhi[nf]);
#pragma unroll
            for (int mf = 0; mf < 4; mf++)
#pragma unroll
                for (int nf = 0; nf < 8; nf++)
                    MMA16816(acc[mf][nf], ahi[mf], blo[nf]);
            if (TERMS == 3) {
#pragma unroll
                for (int mf = 0; mf < 4; mf++)
#pragma unroll
                    for (int nf = 0; nf < 8; nf++)
                        MMA16816(acc[mf][nf], alo[mf], bhi[nf]);
            }
        }

        if (c == NC - 1) {
            int col_base = (bxg * TILES + tile) * 128 + warp_n * 64 + (lane & 3) * 2;
            int row_base = by * 256 + warp_m * 64 + (lane >> 2);
            int contrib = warp_n * 4 + (lane & 3);
#pragma unroll
            for (int mf = 0; mf < 4; mf++) {
                float lsA = 0.f, lqA = 0.f, lsB = 0.f, lqB = 0.f;
#pragma unroll
                for (int nf = 0; nf < 8; nf++) {
                    int col = col_base + nf * 8;
                    float b0 = __ldg(bias + col), b1 = __ldg(bias + col + 1);
                    int r0 = row_base + mf * 16;
                    float2 v0 = { acc[mf][nf][0] + b0, acc[mf][nf][1] + b1 };
                    float2 v1 = { acc[mf][nf][2] + b0, acc[mf][nf][3] + b1 };
                    *(float2*)(C + (size_t)r0 * NTOT + col) = v0;
                    *(float2*)(C + (size_t)(r0 + 8) * NTOT + col) = v1;
                    lsA += v0.x + v0.y; lqA += v0.x * v0.x + v0.y * v0.y;
                    lsB += v1.x + v1.y; lqB += v1.x * v1.x + v1.y * v1.y;
                }
                int rA = warp_m * 64 + mf * 16 + (lane >> 2);
                ssum[rA * 8 + contrib] = lsA;
                ssq [rA * 8 + contrib] = lqA;
                ssum[(rA + 8) * 8 + contrib] = lsB;
                ssq [(rA + 8) * 8 + contrib] = lqB;
#pragma unroll
                for (int nf = 0; nf < 8; nf++)
#pragma unroll
                    for (int q = 0; q < 4; q++) acc[mf][nf][q] = 0.0f;
            }
            __syncthreads();
            {
                float s = 0.f, q = 0.f;
#pragma unroll
                for (int p = 0; p < 8; p++) { s += ssum[tid * 8 + p]; q += ssq[tid * 8 + p]; }
                int tcol = bxg * TILES + tile;
                size_t row = (size_t)(by * 256 + tid);
                psum[row * 8 + tcol] = s;   // uniform stride 8
                psq [row * 8 + tcol] = q;
            }
            __syncthreads();
        }
    }
}

// ---------------------------------------------------------------------------
// Fused stats + LIF: one block per (batch, channel-quarter) -> 1024 blocks.
// Scalar channel per thread. EXACT R15 body (no manual prefetch).
// ---------------------------------------------------------------------------
__global__ void __launch_bounds__(256)
lif_fused(const float* __restrict__ h,
          const float* __restrict__ psum, const float* __restrict__ psq,
          const float* __restrict__ gam, const float* __restrict__ bet,
          __half* __restrict__ spk) {
    __shared__ float smean[256], srstd[256];
    int tid = threadIdx.x;
    int b = blockIdx.x >> 2, qh = blockIdx.x & 3;
    {
        size_t row = (size_t)b * 256 + tid;
        float s = 0.f, q = 0.f;
#pragma unroll
        for (int p = 0; p < 8; p++) { s += psum[row * 8 + p]; q += psq[row * 8 + p]; }
        float m = s * (1.0f / Hsz);
        float var = fmaxf(q * (1.0f / Hsz) - m * m, 0.0f);
        smean[tid] = m;
        srstd[tid] = 1.0f / sqrtf(var + 1e-5f);
    }
    __syncthreads();

    int j = qh * 256 + tid;
    float gg = gam[j], bb = bet[j];
    float v = 0.f;
    size_t base = (size_t)b * Tsz * Hsz + j;
#pragma unroll 4
    for (int t = 0; t < Tsz; t++) {
        float xi = h[base + (size_t)t * Hsz];
        float m = smean[t], inv = srstd[t];
        float n = (xi - m) * inv * gg + bb;
        v = v + (n - v) * 0.5f;
        float sp = 0.f;
        if (v >= 1.0f) { sp = 1.0f; v = 0.f; }
        spk[base + (size_t)t * Hsz] = __float2half_rn(sp);
    }
}

// Fused stats + LIF + residual add + sparse split refresh.
// EXACT R15 body; LAST peels the final timestep OUT of the loop and emits
// out[b,e] value-identically to the old last_kernel.
template <bool LAST>
__global__ void __launch_bounds__(256)
lifadd_fused(const float* __restrict__ h,
             const float* __restrict__ psum, const float* __restrict__ psq,
             const float* __restrict__ gam, const float* __restrict__ bet,
             float* __restrict__ x, __half* __restrict__ xhi,
             __half* __restrict__ xlo, float* __restrict__ out) {
    __shared__ float smean[256], srstd[256];
    int tid = threadIdx.x;
    int b = blockIdx.x >> 1, hh = blockIdx.x & 1;
    {
        size_t row = (size_t)b * 256 + tid;
        float s = 0.f, q = 0.f;
#pragma unroll
        for (int p = 0; p < 4; p++) { s += psum[row * 8 + p]; q += psq[row * 8 + p]; }
        float m = s * (1.0f / Esz);
        float var = fmaxf(q * (1.0f / Esz) - m * m, 0.0f);
        smean[tid] = m;
        srstd[tid] = 1.0f / sqrtf(var + 1e-5f);
    }
    __syncthreads();

    int j = hh * 256 + tid;
    float gg = gam[j], bb = bet[j];
    float v = 0.f;
    size_t base = (size_t)b * Tsz * Esz + j;
    constexpr int TL = LAST ? (Tsz - 1) : Tsz;
#pragma unroll 4
    for (int t = 0; t < TL; t++) {
        float xi = h[base + (size_t)t * Esz];
        float m = smean[t], inv = srstd[t];
        float n = (xi - m) * inv * gg + bb;
        v = v + (n - v) * 0.5f;
        if (v >= 1.0f) {
            v = 0.f;
            size_t o = base + (size_t)t * Esz;
            float xv = x[o] + 1.0f;
            x[o] = xv;
            __half hv = __float2half_rn(xv);
            xhi[o] = hv;
            xlo[o] = __float2half_rn(xv - __half2float(hv));
        }
    }
    if (LAST) {
        const int t = Tsz - 1;
        float xi = h[base + (size_t)t * Esz];
        float m = smean[t], inv = srstd[t];
        float n = (xi - m) * inv * gg + bb;
        v = v + (n - v) * 0.5f;
        size_t o = base + (size_t)t * Esz;
        float xv = x[o];
        if (v >= 1.0f) {
            xv += 1.0f;
            x[o] = xv;
            __half hv = __float2half_rn(xv);
            xhi[o] = hv;
            xlo[o] = __float2half_rn(xv - __half2float(hv));
        }
        out[(size_t)b * Esz + j] = xv;
    }
}

// ---------------------------------------------------------------------------
// Input projector, tiled (16 rows/block, W2 read once per block)
// ---------------------------------------------------------------------------
#define PR 16
__global__ void __launch_bounds__(256)
proj_kernel(const float* __restrict__ hist,
            const float* __restrict__ W1, const float* __restrict__ b1,
            const float* __restrict__ W2, const float* __restrict__ b2,
            float* __restrict__ out,
            __half* __restrict__ ohi, __half* __restrict__ olo) {
    __shared__ float hs[PR * INsz];
    __shared__ float hpT[HPsz][PR];
    int rb = blockIdx.x * PR;
    int tid = threadIdx.x;

    if (tid < PR * INsz) hs[tid] = hist[(size_t)rb * INsz + tid];
    __syncthreads();

#pragma unroll
    for (int i = 0; i < (PR * HPsz) / 256; i++) {
        int idx = tid + i * 256;
        int r = idx >> 6, cc = idx & 63;
        float a = b1[cc];
#pragma unroll
        for (int k = 0; k < INsz; k++) a += hs[r * INsz + k] * W1[k * HPsz + cc];
        hpT[cc][r] = 0.5f * a * (1.0f + erff(a * 0.70710678118654752440f));
    }
    __syncthreads();

    int c0 = tid * 2;
    float acc[PR][2];
    float bb0 = b2[c0], bb1 = b2[c0 + 1];
#pragma unroll
    for (int r = 0; r < PR; r++) { acc[r][0] = bb0; acc[r][1] = bb1; }

    for (int k = 0; k < HPsz; k++) {
        float2 w = *(const float2*)(W2 + (size_t)k * Esz + c0);
        float4 h0 = *(const float4*)&hpT[k][0];
        float4 h1 = *(const float4*)&hpT[k][4];
        float4 h2 = *(const float4*)&hpT[k][8];
        float4 h3 = *(const float4*)&hpT[k][12];
        float hk[PR] = { h0.x, h0.y, h0.z, h0.w, h1.x, h1.y, h1.z, h1.w,
                         h2.x, h2.y, h2.z, h2.w, h3.x, h3.y, h3.z, h3.w };
#pragma unroll
        for (int r = 0; r < PR; r++) {
            acc[r][0] += hk[r] * w.x;
            acc[r][1] += hk[r] * w.y;
        }
    }

#pragma unroll
    for (int r = 0; r < PR; r++) {
        size_t off = (size_t)(rb + r) * Esz + c0;
        float a0 = acc[r][0], a1 = acc[r][1];
        *(float2*)(out + off) = make_float2(a0, a1);
        __half h0 = __float2half_rn(a0), h1 = __float2half_rn(a1);
        *(__half2*)(ohi + off) = __halves2half2(h0, h1);
        *(__half2*)(olo + off) = __halves2half2(
            __float2half_rn(a0 - __half2float(h0)),
            __float2half_rn(a1 - __half2float(h1)));
    }
}

// ---------------------------------------------------------------------------
extern "C" void kernel_launch(void* const* d_in, const int* in_sizes, int n_in,
                              void* d_out, int out_size) {
    const float* hist  = (const float*)d_in[0];
    const float* pW1   = (const float*)d_in[1];
    const float* pb1   = (const float*)d_in[2];
    const float* pW2   = (const float*)d_in[3];
    const float* pb2   = (const float*)d_in[4];
    const float* fc1_w = (const float*)d_in[5];
    const float* fc1_b = (const float*)d_in[6];
    const float* ln1_g = (const float*)d_in[7];
    const float* ln1_b = (const float*)d_in[8];
    const float* fc2_w = (const float*)d_in[9];
    const float* fc2_b = (const float*)d_in[10];
    const float* ln2_g = (const float*)d_in[11];
    const float* ln2_b = (const float*)d_in[12];

    float *x, *h1, *h2, *psum, *psq;
    __half *xhi, *xlo, *spk, *w1hi, *w1lo, *w2hi, *w2lo;
    cudaGetSymbolAddress((void**)&x,    g_x);
    cudaGetSymbolAddress((void**)&h1,   g_h1);
    cudaGetSymbolAddress((void**)&h2,   g_h2);
    cudaGetSymbolAddress((void**)&psum, g_psum);
    cudaGetSymbolAddress((void**)&psq,  g_psq);
    cudaGetSymbolAddress((void**)&xhi,  g_xhi);
    cudaGetSymbolAddress((void**)&xlo,  g_xlo);
    cudaGetSymbolAddress((void**)&spk,  g_spk);
    cudaGetSymbolAddress((void**)&w1hi, g_w1hi);
    cudaGetSymbolAddress((void**)&w1lo, g_w1lo);
    cudaGetSymbolAddress((void**)&w2hi, g_w2hi);
    cudaGetSymbolAddress((void**)&w2lo, g_w2lo);

    auto* gk1 = gemm_hs256<3, 2, Esz, Hsz>;   // GEMM1: 2 N-tiles/CTA
    auto* gk2 = gemm_hs256<2, 1, Hsz, Esz>;   // GEMM2: 1 N-tile/CTA
    cudaFuncSetAttribute(gk1, cudaFuncAttributeMaxDynamicSharedMemorySize, G2<3>::TOT);
    cudaFuncSetAttribute(gk2, cudaFuncAttributeMaxDynamicSharedMemorySize, G2<2>::TOT);

    split_w<<<dim3((Esz * Hsz + 255) / 256, Dsz), 256>>>(fc1_w, w1hi, w1lo, Esz, Hsz);
    split_w<<<dim3((Hsz * Esz + 255) / 256, Dsz), 256>>>(fc2_w, w2hi, w2lo, Hsz, Esz);

    proj_kernel<<<ROWS / PR, 256>>>(hist, pW1, pb1, pW2, pb2, x, xhi, xlo);

    for (int d = 0; d < Dsz; d++) {
        size_t o1 = (size_t)d * Hsz * Esz;
        size_t o2 = (size_t)d * Esz * Hsz;

        gk1<<<dim3(Hsz / 128 / 2, ROWS / 256), 256, G2<3>::TOT>>>(
            xhi, xlo, w1hi + o1, w1lo + o1, fc1_b + d * Hsz, h1, psum, psq);
        lif_fused<<<Bsz * 4, 256>>>(
            h1, psum, psq, ln1_g + d * Hsz, ln1_b + d * Hsz, spk);

        gk2<<<dim3(Esz / 128, ROWS / 256), 256, G2<2>::TOT>>>(
            spk, spk, w2hi + o2, w2lo + o2, fc2_b + d * Esz, h2, psum, psq);
        if (d < Dsz - 1) {
            lifadd_fused<false><<<Bsz * 2, 256>>>(
                h2, psum, psq, ln2_g + d * Esz, ln2_b + d * Esz, x, xhi, xlo, nullptr);
        } else {
            lifadd_fused<true><<<Bsz * 2, 256>>>(
                h2, psum, psq, ln2_g + d * Esz, ln2_b + d * Esz, x, xhi, xlo,
                (float*)d_out);
        }
    }
}